// round 1
// baseline (speedup 1.0000x reference)
#include <cuda_runtime.h>

// Fixed problem shape
#define BATCH 8
#define SEQ   2048
#define DIM   64
#define TQ    16      // queries per CTA
#define TK    256     // keys per K-tile staged in smem
#define NTHR  256
#define KPAD  68      // padded row stride (floats) for K tile -> conflict-free LDS.128

// smem (floats):
//   s_scores [TQ*SEQ]        32768
//   s_q      [TQ*DIM]         1024
//   s_k      [TK*KPAD]       17408
//   s_mask   [SEQ]            2048
//   s_inv    [TQ]               16
#define SMEM_FLOATS (TQ*SEQ + TQ*DIM + TK*KPAD + SEQ + TQ)

__global__ void __launch_bounds__(NTHR, 1)
attn_fused_kernel(const float* __restrict__ key,
                  const float* __restrict__ query,
                  const float* __restrict__ value,
                  const int*   __restrict__ qmask,
                  float* __restrict__ out_ctx,
                  float* __restrict__ out_attn)
{
    extern __shared__ float sm[];
    float* s_scores = sm;                      // TQ*SEQ
    float* s_q      = s_scores + TQ*SEQ;       // TQ*DIM
    float* s_k      = s_q + TQ*DIM;            // TK*KPAD
    float* s_mask   = s_k + TK*KPAD;           // SEQ
    float* s_inv    = s_mask + SEQ;            // TQ

    const int b  = blockIdx.y;
    const int q0 = blockIdx.x * TQ;
    const int t  = threadIdx.x;

    // ---- load Q tile (pre-scaled by 1/sqrt(D) = 0.125) ----
    {
        const float4* qg = (const float4*)(query + ((size_t)b*SEQ + q0)*DIM);
        #pragma unroll
        for (int i = t; i < TQ*DIM/4; i += NTHR) {
            float4 v = qg[i];
            v.x *= 0.125f; v.y *= 0.125f; v.z *= 0.125f; v.w *= 0.125f;
            ((float4*)s_q)[i] = v;
        }
    }
    // ---- load mask as float flags (1.0 = masked -> P=0) ----
    {
        const int* mg = qmask + (size_t)b*SEQ;
        for (int i = t; i < SEQ; i += NTHR)
            s_mask[i] = (mg[i] != 0) ? 1.0f : 0.0f;
    }

    // ---- QK^T: stream K tiles through smem ----
    const int qg_id = t >> 6;   // 0..3 -> q rows 4*qg_id..+3
    const int kg_id = t & 63;   // keys kg_id + 64*i  (lane-stride-1 rows)

    for (int kt = 0; kt < SEQ; kt += TK) {
        __syncthreads();
        // stage K tile [TK][DIM] -> s_k[k][KPAD]
        const float4* kgm = (const float4*)(key + ((size_t)b*SEQ + kt)*DIM);
        #pragma unroll
        for (int i = t; i < TK*DIM/4; i += NTHR) {
            int kk = i >> 4;          // row (16 float4 per row)
            int dv = i & 15;
            *(float4*)(s_k + kk*KPAD + dv*4) = kgm[i];
        }
        __syncthreads();

        float acc[4][4];
        #pragma unroll
        for (int qi = 0; qi < 4; qi++)
            #pragma unroll
            for (int ki = 0; ki < 4; ki++) acc[qi][ki] = 0.0f;

        #pragma unroll
        for (int d4 = 0; d4 < DIM; d4 += 4) {
            float4 qv[4], kv[4];
            #pragma unroll
            for (int qi = 0; qi < 4; qi++)
                qv[qi] = *(const float4*)(s_q + (4*qg_id + qi)*DIM + d4);
            #pragma unroll
            for (int ki = 0; ki < 4; ki++)
                kv[ki] = *(const float4*)(s_k + (kg_id + 64*ki)*KPAD + d4);
            #pragma unroll
            for (int qi = 0; qi < 4; qi++)
                #pragma unroll
                for (int ki = 0; ki < 4; ki++) {
                    acc[qi][ki] = fmaf(qv[qi].x, kv[ki].x, acc[qi][ki]);
                    acc[qi][ki] = fmaf(qv[qi].y, kv[ki].y, acc[qi][ki]);
                    acc[qi][ki] = fmaf(qv[qi].z, kv[ki].z, acc[qi][ki]);
                    acc[qi][ki] = fmaf(qv[qi].w, kv[ki].w, acc[qi][ki]);
                }
        }
        #pragma unroll
        for (int qi = 0; qi < 4; qi++)
            #pragma unroll
            for (int ki = 0; ki < 4; ki++)
                s_scores[(4*qg_id + qi)*SEQ + kt + kg_id + 64*ki] = acc[qi][ki];
    }
    __syncthreads();

    // ---- softmax over keys (mask -> -inf -> weight 0); store exp() back ----
    {
        const int warp = t >> 5, lane = t & 31;
        for (int r = warp; r < TQ; r += NTHR/32) {
            float* row = s_scores + r*SEQ;
            float m = -1e30f;
            for (int j = lane; j < SEQ; j += 32) {
                float s = row[j];
                if (s_mask[j] == 0.0f) m = fmaxf(m, s);
            }
            #pragma unroll
            for (int o = 16; o > 0; o >>= 1)
                m = fmaxf(m, __shfl_xor_sync(0xffffffffu, m, o));
            float sum = 0.0f;
            for (int j = lane; j < SEQ; j += 32) {
                float s = row[j];
                float e = (s_mask[j] == 0.0f) ? __expf(s - m) : 0.0f;
                row[j] = e;
                sum += e;
            }
            #pragma unroll
            for (int o = 16; o > 0; o >>= 1)
                sum += __shfl_xor_sync(0xffffffffu, sum, o);
            if (lane == 0) s_inv[r] = 1.0f / sum;
        }
    }
    __syncthreads();

    // ---- write normalized attention matrix to gmem ----
    {
        float* abase = out_attn + ((size_t)b*SEQ + q0)*SEQ;
        #pragma unroll 4
        for (int i = t; i < TQ*SEQ/4; i += NTHR) {
            int r = i >> 9;          // / (SEQ/4)
            int c = i & 511;
            float inv = s_inv[r];
            float4 e = ((const float4*)(s_scores + r*SEQ))[c];
            e.x *= inv; e.y *= inv; e.z *= inv; e.w *= inv;
            ((float4*)(abase + (size_t)r*SEQ))[c] = e;
        }
    }

    // ---- context = P @ V  (V from gmem / L2, P broadcast from smem) ----
    {
        const int qr = t >> 4;       // 0..15 query row
        const int dq = t & 15;       // float4 column of D
        const float4* vg = (const float4*)(value + (size_t)b*SEQ*DIM) + dq;
        const float* prow = s_scores + qr*SEQ;
        float4 acc = make_float4(0.f, 0.f, 0.f, 0.f);
        for (int k = 0; k < SEQ; k += 8) {
            float4 p0 = *(const float4*)(prow + k);
            float4 p1 = *(const float4*)(prow + k + 4);
            float4 v[8];
            #pragma unroll
            for (int i = 0; i < 8; i++) v[i] = vg[(size_t)(k + i) * (DIM/4)];
            float pc[8] = {p0.x, p0.y, p0.z, p0.w, p1.x, p1.y, p1.z, p1.w};
            #pragma unroll
            for (int i = 0; i < 8; i++) {
                acc.x = fmaf(pc[i], v[i].x, acc.x);
                acc.y = fmaf(pc[i], v[i].y, acc.y);
                acc.z = fmaf(pc[i], v[i].z, acc.z);
                acc.w = fmaf(pc[i], v[i].w, acc.w);
            }
        }
        float inv = s_inv[qr];
        acc.x *= inv; acc.y *= inv; acc.z *= inv; acc.w *= inv;
        *(float4*)(out_ctx + ((size_t)b*SEQ + q0 + qr)*DIM + dq*4) = acc;
    }
}

extern "C" void kernel_launch(void* const* d_in, const int* in_sizes, int n_in,
                              void* d_out, int out_size)
{
    const float* key   = (const float*)d_in[0];
    const float* query = (const float*)d_in[1];
    const float* value = (const float*)d_in[2];
    const int*   qmask = (const int*)d_in[3];

    float* out_ctx  = (float*)d_out;                                  // [B,S,D]
    float* out_attn = (float*)d_out + (size_t)BATCH*SEQ*DIM;          // [B,S,S]

    const size_t smem = (size_t)SMEM_FLOATS * sizeof(float);
    cudaFuncSetAttribute(attn_fused_kernel,
                         cudaFuncAttributeMaxDynamicSharedMemorySize, (int)smem);

    dim3 grid(SEQ / TQ, BATCH);
    attn_fused_kernel<<<grid, NTHR, smem>>>(key, query, value, qmask,
                                            out_ctx, out_attn);
}

// round 2
// speedup vs baseline: 2.2798x; 2.2798x over previous
#include <cuda_runtime.h>

#define BATCH 8
#define SEQ   2048
#define DIM   64
#define TQ    64      // queries per CTA
#define TK    64      // keys per tile
#define NTHR  256
#define ROWP  68      // padded row stride (floats) for Q/K/V tiles

// smem floats: sQ 64*68 + sK 64*68 + sV 64*68 + sE 64*64 = 17152 floats
// + mask 2048 bytes
#define SMEM_BYTES ((64*ROWP*3 + 64*64)*4 + SEQ)

__device__ float g_inv[BATCH*SEQ];

// packed f32x2 FMA: d = a*b + d (elementwise on packed pairs)
#define FMA2(d, a, b) asm("fma.rn.f32x2 %0, %1, %2, %0;" : "+l"(d) : "l"(a), "l"(b))
__device__ __forceinline__ unsigned long long pack2(float lo, float hi) {
    unsigned long long r;
    asm("mov.b64 %0, {%1, %2};" : "=l"(r) : "f"(lo), "f"(hi));
    return r;
}
__device__ __forceinline__ float lo32(unsigned long long u) { return __uint_as_float((unsigned)u); }
__device__ __forceinline__ float hi32(unsigned long long u) { return __uint_as_float((unsigned)(u >> 32)); }

__global__ void __launch_bounds__(NTHR, 3)
attn_main_kernel(const float* __restrict__ key,
                 const float* __restrict__ query,
                 const float* __restrict__ value,
                 const int*   __restrict__ qmask,
                 float* __restrict__ out_ctx,
                 float* __restrict__ out_attn)
{
    extern __shared__ float sm[];
    float* sQ = sm;                       // [64][68]
    float* sK = sQ + 64*ROWP;             // [64][68]
    float* sV = sK + 64*ROWP;             // [64][68]
    float* sE = sV + 64*ROWP;             // [64][64]
    unsigned char* sM = (unsigned char*)(sE + 64*64);  // [2048]

    const int b  = blockIdx.y;
    const int q0 = blockIdx.x * TQ;
    const int t  = threadIdx.x;
    const int ty = t >> 4;                // 0..15 -> q rows 4*ty..+3
    const int tx = t & 15;                // 0..15

    // ---- stage Q (scaled by 1/sqrt(64) = 0.125), mask flags ----
    {
        const float4* qg = (const float4*)(query + ((size_t)b*SEQ + q0)*DIM);
        #pragma unroll
        for (int i = t; i < TQ*DIM/4; i += NTHR) {
            int r = i >> 4, c = i & 15;
            float4 v = qg[i];
            v.x *= 0.125f; v.y *= 0.125f; v.z *= 0.125f; v.w *= 0.125f;
            *(float4*)(sQ + r*ROWP + c*4) = v;
        }
        const int* mg = qmask + (size_t)b*SEQ;
        for (int i = t; i < SEQ; i += NTHR)
            sM[i] = (unsigned char)(mg[i] != 0);
    }

    unsigned long long ctx2[4][2];
    #pragma unroll
    for (int qi = 0; qi < 4; qi++) { ctx2[qi][0] = 0ull; ctx2[qi][1] = 0ull; }
    float rowsum[4] = {0.f, 0.f, 0.f, 0.f};

    const float* kg_base = key   + (size_t)b*SEQ*DIM;
    const float* vg_base = value + (size_t)b*SEQ*DIM;
    float* attn_base = out_attn + ((size_t)b*SEQ + q0)*SEQ;

    for (int kt = 0; kt < SEQ; kt += TK) {
        __syncthreads();   // prev PV / e-write done before overwriting tiles
        // ---- stage K,V tiles [64][64] -> [64][68] ----
        {
            const float4* kg = (const float4*)(kg_base + (size_t)kt*DIM);
            const float4* vg = (const float4*)(vg_base + (size_t)kt*DIM);
            #pragma unroll
            for (int i = t; i < TK*DIM/4; i += NTHR) {
                int r = i >> 4, c = i & 15;
                *(float4*)(sK + r*ROWP + c*4) = kg[i];
                *(float4*)(sV + r*ROWP + c*4) = vg[i];
            }
        }
        __syncthreads();

        // ---- QK^T: thread tile 4q x 4k (k = tx + 16j), packed f32x2 ----
        unsigned long long acc[16];
        #pragma unroll
        for (int i = 0; i < 16; i++) acc[i] = 0ull;

        #pragma unroll 4
        for (int d4 = 0; d4 < 16; d4++) {
            ulonglong2 k2[4];
            #pragma unroll
            for (int j = 0; j < 4; j++)
                k2[j] = *(const ulonglong2*)(sK + (tx + 16*j)*ROWP + d4*4);
            #pragma unroll
            for (int qi = 0; qi < 4; qi++) {
                ulonglong2 q2 = *(const ulonglong2*)(sQ + (4*ty + qi)*ROWP + d4*4);
                #pragma unroll
                for (int j = 0; j < 4; j++) {
                    FMA2(acc[qi*4 + j], q2.x, k2[j].x);
                    FMA2(acc[qi*4 + j], q2.y, k2[j].y);
                }
            }
        }
        // ---- exp + mask, STS to sE, rowsum ----
        #pragma unroll
        for (int j = 0; j < 4; j++) {
            int kk = tx + 16*j;
            unsigned char flag = sM[kt + kk];
            #pragma unroll
            for (int qi = 0; qi < 4; qi++) {
                unsigned long long a = acc[qi*4 + j];
                float s = lo32(a) + hi32(a);
                float e = flag ? 0.0f : __expf(s);
                rowsum[qi] += e;
                sE[(4*ty + qi)*64 + kk] = e;
            }
        }
        __syncthreads();

        // ---- write unnormalized e tile to gmem (coalesced) ----
        #pragma unroll
        for (int i = t; i < TQ*TK/4; i += NTHR) {
            int r = i >> 4, c = i & 15;
            float4 e4 = *(const float4*)(sE + r*64 + c*4);
            *(float4*)(attn_base + (size_t)r*SEQ + kt + c*4) = e4;
        }

        // ---- PV: ctx[4q][d=4tx..+3] += e * V ----
        #pragma unroll 2
        for (int k = 0; k < TK; k++) {
            ulonglong2 v2 = *(const ulonglong2*)(sV + k*ROWP + tx*4);
            #pragma unroll
            for (int qi = 0; qi < 4; qi++) {
                float e = sE[(4*ty + qi)*64 + k];
                unsigned long long ee = pack2(e, e);
                FMA2(ctx2[qi][0], ee, v2.x);
                FMA2(ctx2[qi][1], ee, v2.y);
            }
        }
    }

    // ---- reduce rowsums across tx (16-lane groups), write inv, store ctx ----
    #pragma unroll
    for (int qi = 0; qi < 4; qi++) {
        float s = rowsum[qi];
        #pragma unroll
        for (int o = 8; o > 0; o >>= 1)
            s += __shfl_down_sync(0xffffffffu, s, o, 16);
        s = __shfl_sync(0xffffffffu, s, 0, 16);   // broadcast group sum
        float inv = 1.0f / s;
        if (tx == 0) g_inv[(size_t)b*SEQ + q0 + 4*ty + qi] = inv;
        float4 c;
        c.x = lo32(ctx2[qi][0]) * inv;
        c.y = hi32(ctx2[qi][0]) * inv;
        c.z = lo32(ctx2[qi][1]) * inv;
        c.w = hi32(ctx2[qi][1]) * inv;
        *(float4*)(out_ctx + ((size_t)b*SEQ + q0 + 4*ty + qi)*DIM + tx*4) = c;
    }
}

// normalize attention rows: attn[row][:] *= g_inv[row]
__global__ void __launch_bounds__(256)
attn_scale_kernel(float* __restrict__ attn)
{
    const int row = blockIdx.x;
    const float s = g_inv[row];
    float4* p = (float4*)(attn + (size_t)row*SEQ);
    #pragma unroll
    for (int i = threadIdx.x; i < SEQ/4; i += 256) {
        float4 v = p[i];
        v.x *= s; v.y *= s; v.z *= s; v.w *= s;
        p[i] = v;
    }
}

extern "C" void kernel_launch(void* const* d_in, const int* in_sizes, int n_in,
                              void* d_out, int out_size)
{
    const float* key   = (const float*)d_in[0];
    const float* query = (const float*)d_in[1];
    const float* value = (const float*)d_in[2];
    const int*   qmask = (const int*)d_in[3];

    float* out_ctx  = (float*)d_out;
    float* out_attn = (float*)d_out + (size_t)BATCH*SEQ*DIM;

    cudaFuncSetAttribute(attn_main_kernel,
                         cudaFuncAttributeMaxDynamicSharedMemorySize, SMEM_BYTES);

    dim3 grid(SEQ / TQ, BATCH);
    attn_main_kernel<<<grid, NTHR, SMEM_BYTES>>>(key, query, value, qmask,
                                                 out_ctx, out_attn);
    attn_scale_kernel<<<BATCH*SEQ, 256>>>(out_attn);
}

// round 3
// speedup vs baseline: 2.2822x; 1.0011x over previous
#include <cuda_runtime.h>

#define BATCH 8
#define SEQ   2048
#define DIM   64
#define TQ    64      // queries per CTA
#define TK    64      // keys per tile
#define NTHR  256
#define ROWP  68      // padded row stride (floats) for Q/K/V tiles

// smem floats: sQ 64*68 + sK 64*68 + sV 64*68 + sE 64*64 = 17152 floats
// + mask 2048 bytes
#define SMEM_BYTES ((64*ROWP*3 + 64*64)*4 + SEQ)

__device__ float g_inv[BATCH*SEQ];

// packed f32x2 FMA: d = a*b + d (elementwise on packed pairs)
#define FMA2(d, a, b) asm("fma.rn.f32x2 %0, %1, %2, %0;" : "+l"(d) : "l"(a), "l"(b))
__device__ __forceinline__ unsigned long long pack2(float lo, float hi) {
    unsigned long long r;
    asm("mov.b64 %0, {%1, %2};" : "=l"(r) : "f"(lo), "f"(hi));
    return r;
}
__device__ __forceinline__ float lo32(unsigned long long u) { return __uint_as_float((unsigned)u); }
__device__ __forceinline__ float hi32(unsigned long long u) { return __uint_as_float((unsigned)(u >> 32)); }

__global__ void __launch_bounds__(NTHR, 3)
attn_main_kernel(const float* __restrict__ key,
                 const float* __restrict__ query,
                 const float* __restrict__ value,
                 const int*   __restrict__ qmask,
                 float* __restrict__ out_ctx,
                 float* __restrict__ out_attn)
{
    extern __shared__ float sm[];
    float* sQ = sm;                       // [64][68]
    float* sK = sQ + 64*ROWP;             // [64][68]
    float* sV = sK + 64*ROWP;             // [64][68]
    float* sE = sV + 64*ROWP;             // [64][64]
    unsigned char* sM = (unsigned char*)(sE + 64*64);  // [2048]

    const int b  = blockIdx.y;
    const int q0 = blockIdx.x * TQ;
    const int t  = threadIdx.x;
    const int ty = t >> 4;                // 0..15 -> q rows 4*ty..+3
    const int tx = t & 15;                // 0..15

    // ---- stage Q (scaled by 1/sqrt(64) = 0.125), mask flags ----
    {
        const float4* qg = (const float4*)(query + ((size_t)b*SEQ + q0)*DIM);
        #pragma unroll
        for (int i = t; i < TQ*DIM/4; i += NTHR) {
            int r = i >> 4, c = i & 15;
            float4 v = qg[i];
            v.x *= 0.125f; v.y *= 0.125f; v.z *= 0.125f; v.w *= 0.125f;
            *(float4*)(sQ + r*ROWP + c*4) = v;
        }
        const int* mg = qmask + (size_t)b*SEQ;
        for (int i = t; i < SEQ; i += NTHR)
            sM[i] = (unsigned char)(mg[i] != 0);
    }

    unsigned long long ctx2[4][2];
    #pragma unroll
    for (int qi = 0; qi < 4; qi++) { ctx2[qi][0] = 0ull; ctx2[qi][1] = 0ull; }
    float rowsum[4] = {0.f, 0.f, 0.f, 0.f};

    const float* kg_base = key   + (size_t)b*SEQ*DIM;
    const float* vg_base = value + (size_t)b*SEQ*DIM;
    float* attn_base = out_attn + ((size_t)b*SEQ + q0)*SEQ;

    for (int kt = 0; kt < SEQ; kt += TK) {
        __syncthreads();   // prev PV / e-write done before overwriting tiles
        // ---- stage K,V tiles [64][64] -> [64][68] ----
        {
            const float4* kg = (const float4*)(kg_base + (size_t)kt*DIM);
            const float4* vg = (const float4*)(vg_base + (size_t)kt*DIM);
            #pragma unroll
            for (int i = t; i < TK*DIM/4; i += NTHR) {
                int r = i >> 4, c = i & 15;
                *(float4*)(sK + r*ROWP + c*4) = kg[i];
                *(float4*)(sV + r*ROWP + c*4) = vg[i];
            }
        }
        __syncthreads();

        // ---- QK^T: thread tile 4q x 4k (k = tx + 16j), packed f32x2 ----
        unsigned long long acc[16];
        #pragma unroll
        for (int i = 0; i < 16; i++) acc[i] = 0ull;

        #pragma unroll 4
        for (int d4 = 0; d4 < 16; d4++) {
            ulonglong2 k2[4];
            #pragma unroll
            for (int j = 0; j < 4; j++)
                k2[j] = *(const ulonglong2*)(sK + (tx + 16*j)*ROWP + d4*4);
            #pragma unroll
            for (int qi = 0; qi < 4; qi++) {
                ulonglong2 q2 = *(const ulonglong2*)(sQ + (4*ty + qi)*ROWP + d4*4);
                #pragma unroll
                for (int j = 0; j < 4; j++) {
                    FMA2(acc[qi*4 + j], q2.x, k2[j].x);
                    FMA2(acc[qi*4 + j], q2.y, k2[j].y);
                }
            }
        }
        // ---- exp + mask, STS to sE, rowsum ----
        #pragma unroll
        for (int j = 0; j < 4; j++) {
            int kk = tx + 16*j;
            unsigned char flag = sM[kt + kk];
            #pragma unroll
            for (int qi = 0; qi < 4; qi++) {
                unsigned long long a = acc[qi*4 + j];
                float s = lo32(a) + hi32(a);
                float e = flag ? 0.0f : __expf(s);
                rowsum[qi] += e;
                sE[(4*ty + qi)*64 + kk] = e;
            }
        }
        __syncthreads();

        // ---- write unnormalized e tile to gmem (coalesced) ----
        #pragma unroll
        for (int i = t; i < TQ*TK/4; i += NTHR) {
            int r = i >> 4, c = i & 15;
            float4 e4 = *(const float4*)(sE + r*64 + c*4);
            *(float4*)(attn_base + (size_t)r*SEQ + kt + c*4) = e4;
        }

        // ---- PV: ctx[4q][d=4tx..+3] += e * V ----
        #pragma unroll 2
        for (int k = 0; k < TK; k++) {
            ulonglong2 v2 = *(const ulonglong2*)(sV + k*ROWP + tx*4);
            #pragma unroll
            for (int qi = 0; qi < 4; qi++) {
                float e = sE[(4*ty + qi)*64 + k];
                unsigned long long ee = pack2(e, e);
                FMA2(ctx2[qi][0], ee, v2.x);
                FMA2(ctx2[qi][1], ee, v2.y);
            }
        }
    }

    // ---- reduce rowsums across tx (16-lane groups), write inv, store ctx ----
    #pragma unroll
    for (int qi = 0; qi < 4; qi++) {
        float s = rowsum[qi];
        #pragma unroll
        for (int o = 8; o > 0; o >>= 1)
            s += __shfl_down_sync(0xffffffffu, s, o, 16);
        s = __shfl_sync(0xffffffffu, s, 0, 16);   // broadcast group sum
        float inv = 1.0f / s;
        if (tx == 0) g_inv[(size_t)b*SEQ + q0 + 4*ty + qi] = inv;
        float4 c;
        c.x = lo32(ctx2[qi][0]) * inv;
        c.y = hi32(ctx2[qi][0]) * inv;
        c.z = lo32(ctx2[qi][1]) * inv;
        c.w = hi32(ctx2[qi][1]) * inv;
        *(float4*)(out_ctx + ((size_t)b*SEQ + q0 + 4*ty + qi)*DIM + tx*4) = c;
    }
}

// normalize attention rows: attn[row][:] *= g_inv[row]
__global__ void __launch_bounds__(256)
attn_scale_kernel(float* __restrict__ attn)
{
    const int row = blockIdx.x;
    const float s = g_inv[row];
    float4* p = (float4*)(attn + (size_t)row*SEQ);
    #pragma unroll
    for (int i = threadIdx.x; i < SEQ/4; i += 256) {
        float4 v = p[i];
        v.x *= s; v.y *= s; v.z *= s; v.w *= s;
        p[i] = v;
    }
}

extern "C" void kernel_launch(void* const* d_in, const int* in_sizes, int n_in,
                              void* d_out, int out_size)
{
    const float* key   = (const float*)d_in[0];
    const float* query = (const float*)d_in[1];
    const float* value = (const float*)d_in[2];
    const int*   qmask = (const int*)d_in[3];

    float* out_ctx  = (float*)d_out;
    float* out_attn = (float*)d_out + (size_t)BATCH*SEQ*DIM;

    cudaFuncSetAttribute(attn_main_kernel,
                         cudaFuncAttributeMaxDynamicSharedMemorySize, SMEM_BYTES);

    dim3 grid(SEQ / TQ, BATCH);
    attn_main_kernel<<<grid, NTHR, SMEM_BYTES>>>(key, query, value, qmask,
                                                 out_ctx, out_attn);
    attn_scale_kernel<<<BATCH*SEQ, 256>>>(out_attn);
}